// round 1
// baseline (speedup 1.0000x reference)
#include <cuda_runtime.h>
#include <cstdint>

#define BB 32
#define SS 1024
#define II 128
#define HH 128
#define DD 256   // 2*HH

// ---------------- scratch (static device arrays; allocation-free) -------------
__device__ float g_xg[(size_t)2 * BB * SS * 4 * HH];   // [dir][b][s][4H]  134MB
__device__ float g_h [(size_t)BB * SS * DD];           // [b][s][2H]       33.5MB
__device__ float g_q [(size_t)BB * SS * DD];
__device__ float g_k [(size_t)BB * SS * DD];
__device__ float g_v [(size_t)BB * SS * DD];
__device__ float g_sc[(size_t)BB * SS * SS];           // [b][s][t]        134MB

// =============================================================================
// SGEMM  C = alpha * A @ B^T (+ bias1 + bias2)
// A: [M,K] row-major, B: [N,K] row-major, C: [M,N]. M,N % 64 == 0, K % 16 == 0.
// Batched via blockIdx.z with element strides sA/sB/sC.
// =============================================================================
__global__ __launch_bounds__(256) void sgemm_nt(
    const float* __restrict__ A, const float* __restrict__ B,
    const float* __restrict__ b1, const float* __restrict__ b2,
    float* __restrict__ C, int K, int N,
    long long sA, long long sB, long long sC, float alpha)
{
    A += (size_t)blockIdx.z * sA;
    B += (size_t)blockIdx.z * sB;
    C += (size_t)blockIdx.z * sC;

    __shared__ float As[16][64];
    __shared__ float Bs[16][64];

    const int bm = blockIdx.y * 64;
    const int bn = blockIdx.x * 64;
    const int tid = threadIdx.x;
    const int tx = tid & 15;          // n sub-tile
    const int ty = tid >> 4;          // m sub-tile
    const int lr = tid >> 2;          // 0..63 row for loading
    const int lc = (tid & 3) << 2;    // 0,4,8,12 k offset (float4)

    float acc[4][4];
#pragma unroll
    for (int i = 0; i < 4; i++)
#pragma unroll
        for (int j = 0; j < 4; j++) acc[i][j] = 0.f;

    for (int k0 = 0; k0 < K; k0 += 16) {
        float4 av = *(const float4*)(A + (size_t)(bm + lr) * K + k0 + lc);
        float4 bv = *(const float4*)(B + (size_t)(bn + lr) * K + k0 + lc);
        As[lc + 0][lr] = av.x; As[lc + 1][lr] = av.y;
        As[lc + 2][lr] = av.z; As[lc + 3][lr] = av.w;
        Bs[lc + 0][lr] = bv.x; Bs[lc + 1][lr] = bv.y;
        Bs[lc + 2][lr] = bv.z; Bs[lc + 3][lr] = bv.w;
        __syncthreads();
#pragma unroll
        for (int kk = 0; kk < 16; kk++) {
            float ra[4], rb[4];
            *(float4*)ra = *(const float4*)&As[kk][ty << 2];
            *(float4*)rb = *(const float4*)&Bs[kk][tx << 2];
#pragma unroll
            for (int i = 0; i < 4; i++)
#pragma unroll
                for (int j = 0; j < 4; j++) acc[i][j] += ra[i] * rb[j];
        }
        __syncthreads();
    }

#pragma unroll
    for (int i = 0; i < 4; i++) {
        const int row = bm + (ty << 2) + i;
#pragma unroll
        for (int j = 0; j < 4; j++) {
            const int col = bn + (tx << 2) + j;
            float vv = acc[i][j] * alpha;
            if (b1) vv += b1[col];
            if (b2) vv += b2[col];
            C[(size_t)row * N + col] = vv;
        }
    }
}

// =============================================================================
// SGEMM  C = A @ B   (A: [M,K], B: [K,N] row-major, C: [M,N])
// M,N % 64 == 0, K % 16 == 0. Batched via blockIdx.z.
// =============================================================================
__global__ __launch_bounds__(256) void sgemm_nn(
    const float* __restrict__ A, const float* __restrict__ B,
    float* __restrict__ C, int K, int N,
    long long sA, long long sB, long long sC)
{
    A += (size_t)blockIdx.z * sA;
    B += (size_t)blockIdx.z * sB;
    C += (size_t)blockIdx.z * sC;

    __shared__ float As[16][64];
    __shared__ float Bs[16][64];

    const int bm = blockIdx.y * 64;
    const int bn = blockIdx.x * 64;
    const int tid = threadIdx.x;
    const int tx = tid & 15;
    const int ty = tid >> 4;
    const int lr = tid >> 2;          // A-load row 0..63
    const int lc = (tid & 3) << 2;    // A-load k offset
    const int kr = tid >> 4;          // B-load k row 0..15
    const int nc = (tid & 15) << 2;   // B-load n offset 0..60

    float acc[4][4];
#pragma unroll
    for (int i = 0; i < 4; i++)
#pragma unroll
        for (int j = 0; j < 4; j++) acc[i][j] = 0.f;

    for (int k0 = 0; k0 < K; k0 += 16) {
        float4 av = *(const float4*)(A + (size_t)(bm + lr) * K + k0 + lc);
        As[lc + 0][lr] = av.x; As[lc + 1][lr] = av.y;
        As[lc + 2][lr] = av.z; As[lc + 3][lr] = av.w;
        float4 bv = *(const float4*)(B + (size_t)(k0 + kr) * N + bn + nc);
        *(float4*)&Bs[kr][nc] = bv;
        __syncthreads();
#pragma unroll
        for (int kk = 0; kk < 16; kk++) {
            float ra[4], rb[4];
            *(float4*)ra = *(const float4*)&As[kk][ty << 2];
            *(float4*)rb = *(const float4*)&Bs[kk][tx << 2];
#pragma unroll
            for (int i = 0; i < 4; i++)
#pragma unroll
                for (int j = 0; j < 4; j++) acc[i][j] += ra[i] * rb[j];
        }
        __syncthreads();
    }

#pragma unroll
    for (int i = 0; i < 4; i++) {
        const int row = bm + (ty << 2) + i;
#pragma unroll
        for (int j = 0; j < 4; j++) {
            const int col = bn + (tx << 2) + j;
            C[(size_t)row * N + col] = acc[i][j];
        }
    }
}

// =============================================================================
// LSTM recurrence, both directions. One CTA per (dir, batch): 64 CTAs x 512 thr.
// Thread g owns gate row g of Whh[4H, H]:
//   K 0..95  : packed f32x2 pairs in registers (48 x u64 = 96 regs)
//   K 96..127: SMEM, transposed [j2][g] as u64 pairs (conflict-free)
// Per step: dot(h, Whh_row) via fma.rn.f32x2, barrier, 128 threads do gate math.
// =============================================================================
#define LSTM_SMEM ((128 + 512) * 4 + 16 * 512 * 8)

__device__ __forceinline__ void fma2(unsigned long long& d,
                                     unsigned long long a,
                                     unsigned long long b)
{
    asm("fma.rn.f32x2 %0, %1, %2, %0;" : "+l"(d) : "l"(a), "l"(b));
}

__device__ __forceinline__ float sum2(unsigned long long a)
{
    return __uint_as_float((unsigned)a) + __uint_as_float((unsigned)(a >> 32));
}

__global__ __launch_bounds__(512) void lstm_kernel(
    const float* __restrict__ xg_all,
    const float* __restrict__ Whh_fw,
    const float* __restrict__ Whh_bw,
    float* __restrict__ Hout)
{
    extern __shared__ float sm[];
    float* h_sh = sm;                                        // 128 floats
    float* gate = sm + 128;                                  // 512 floats
    unsigned long long* w_sh2 = (unsigned long long*)(sm + 640); // 16*512 u64

    const int dir = blockIdx.x >> 5;
    const int b   = blockIdx.x & 31;
    const int g   = threadIdx.x;
    const float* Whh = dir ? Whh_bw : Whh_fw;

    // register half: K 0..95 (48 f32x2 pairs)
    unsigned long long w2[48];
    {
        const unsigned long long* wr =
            (const unsigned long long*)(Whh + (size_t)g * HH);
#pragma unroll
        for (int i = 0; i < 48; i++) w2[i] = wr[i];
    }
    // shared half: K 96..127, transposed [j2][g], pairs
    for (int idx = g; idx < 16 * 512; idx += 512) {
        const int j2 = idx >> 9;
        const int gg = idx & 511;
        w_sh2[idx] =
            *(const unsigned long long*)(Whh + (size_t)gg * HH + 96 + 2 * j2);
    }
    if (g < HH) h_sh[g] = 0.f;
    float c = 0.f;
    __syncthreads();

    const float* xg = xg_all + ((size_t)dir * BB + b) * SS * (4 * HH);

    for (int t = 0; t < SS; t++) {
        const int s = dir ? (SS - 1 - t) : t;
        float acc = xg[(size_t)s * 512 + g];

        unsigned long long a2a = 0ull, a2b = 0ull;
        const ulonglong2* hq = (const ulonglong2*)h_sh;       // 32 x (2 pairs)
#pragma unroll
        for (int i = 0; i < 24; i++) {                        // pairs 0..47
            ulonglong2 hv = hq[i];
            fma2(a2a, w2[2 * i], hv.x);
            fma2(a2b, w2[2 * i + 1], hv.y);
        }
        const unsigned long long* hp = (const unsigned long long*)h_sh;
#pragma unroll
        for (int j2 = 0; j2 < 16; j2++) {                     // pairs 48..63
            unsigned long long wv = w_sh2[j2 * 512 + g];
            if (j2 & 1) fma2(a2b, wv, hp[48 + j2]);
            else        fma2(a2a, wv, hp[48 + j2]);
        }
        acc += sum2(a2a) + sum2(a2b);

        gate[g] = acc;
        __syncthreads();

        if (g < HH) {
            const float i_ = 1.f / (1.f + __expf(-gate[g]));
            const float f_ = 1.f / (1.f + __expf(-gate[HH + g]));
            const float g_ = tanhf(gate[2 * HH + g]);
            const float o_ = 1.f / (1.f + __expf(-gate[3 * HH + g]));
            c = f_ * c + i_ * g_;
            const float h = o_ * tanhf(c);
            h_sh[g] = h;
            Hout[((size_t)b * SS + s) * DD + dir * HH + g] = h;
        }
        __syncthreads();
    }
}

// =============================================================================
// Row softmax over the last axis of g_sc: one CTA per row of 1024.
// =============================================================================
__global__ __launch_bounds__(256) void softmax_rows(float* __restrict__ S)
{
    float* row = S + (size_t)blockIdx.x * SS;
    const int t = threadIdx.x;
    __shared__ float red[8];

    float v0 = row[t], v1 = row[t + 256], v2 = row[t + 512], v3 = row[t + 768];

    float m = fmaxf(fmaxf(v0, v1), fmaxf(v2, v3));
#pragma unroll
    for (int o = 16; o > 0; o >>= 1)
        m = fmaxf(m, __shfl_xor_sync(0xffffffffu, m, o));
    if ((t & 31) == 0) red[t >> 5] = m;
    __syncthreads();
    m = fmaxf(fmaxf(fmaxf(red[0], red[1]), fmaxf(red[2], red[3])),
              fmaxf(fmaxf(red[4], red[5]), fmaxf(red[6], red[7])));

    v0 = __expf(v0 - m); v1 = __expf(v1 - m);
    v2 = __expf(v2 - m); v3 = __expf(v3 - m);
    float s = (v0 + v1) + (v2 + v3);
#pragma unroll
    for (int o = 16; o > 0; o >>= 1)
        s += __shfl_xor_sync(0xffffffffu, s, o);
    __syncthreads();                         // everyone done reading max vals
    if ((t & 31) == 0) red[t >> 5] = s;
    __syncthreads();
    s = ((red[0] + red[1]) + (red[2] + red[3])) +
        ((red[4] + red[5]) + (red[6] + red[7]));
    const float inv = 1.f / s;

    row[t]       = v0 * inv;
    row[t + 256] = v1 * inv;
    row[t + 512] = v2 * inv;
    row[t + 768] = v3 * inv;
}

// =============================================================================
// launch
// =============================================================================
extern "C" void kernel_launch(void* const* d_in, const int* in_sizes, int n_in,
                              void* d_out, int out_size)
{
    const float* x     = (const float*)d_in[0];
    const float* fwWih = (const float*)d_in[1];
    const float* fwWhh = (const float*)d_in[2];
    const float* fwbih = (const float*)d_in[3];
    const float* fwbhh = (const float*)d_in[4];
    const float* bwWih = (const float*)d_in[5];
    const float* bwWhh = (const float*)d_in[6];
    const float* bwbih = (const float*)d_in[7];
    const float* bwbhh = (const float*)d_in[8];
    const float* Wq    = (const float*)d_in[9];
    const float* Wk    = (const float*)d_in[10];
    const float* Wv    = (const float*)d_in[11];
    float* out = (float*)d_out;

    float *xg, *h, *q, *k, *v, *sc;
    cudaGetSymbolAddress((void**)&xg, g_xg);
    cudaGetSymbolAddress((void**)&h,  g_h);
    cudaGetSymbolAddress((void**)&q,  g_q);
    cudaGetSymbolAddress((void**)&k,  g_k);
    cudaGetSymbolAddress((void**)&v,  g_v);
    cudaGetSymbolAddress((void**)&sc, g_sc);

    cudaFuncSetAttribute(lstm_kernel,
                         cudaFuncAttributeMaxDynamicSharedMemorySize, LSTM_SMEM);

    // 1) input projections + biases:  xg[dir] = x @ Wih^T + bih + bhh
    {
        dim3 grid(512 / 64, (BB * SS) / 64, 1);
        sgemm_nt<<<grid, 256>>>(x, fwWih, fwbih, fwbhh, xg,
                                II, 4 * HH, 0, 0, 0, 1.f);
        sgemm_nt<<<grid, 256>>>(x, bwWih, bwbih, bwbhh,
                                xg + (size_t)BB * SS * 4 * HH,
                                II, 4 * HH, 0, 0, 0, 1.f);
    }

    // 2) bidirectional LSTM recurrence -> h [B,S,2H]
    lstm_kernel<<<64, 512, LSTM_SMEM>>>(xg, fwWhh, bwWhh, h);

    // 3) QKV projections
    {
        dim3 grid(DD / 64, (BB * SS) / 64, 1);
        sgemm_nt<<<grid, 256>>>(h, Wq, nullptr, nullptr, q, DD, DD, 0, 0, 0, 1.f);
        sgemm_nt<<<grid, 256>>>(h, Wk, nullptr, nullptr, k, DD, DD, 0, 0, 0, 1.f);
        sgemm_nt<<<grid, 256>>>(h, Wv, nullptr, nullptr, v, DD, DD, 0, 0, 0, 1.f);
    }

    // 4) scores = q @ k^T / sqrt(D)   (batched over B)
    {
        dim3 grid(SS / 64, SS / 64, BB);
        sgemm_nt<<<grid, 256>>>(q, k, nullptr, nullptr, sc, DD, SS,
                                (long long)SS * DD, (long long)SS * DD,
                                (long long)SS * SS, 0.0625f);
    }

    // 5) softmax over last axis
    softmax_rows<<<BB * SS, 256>>>(sc);

    // 6) out = att @ v  (batched)
    {
        dim3 grid(DD / 64, SS / 64, BB);
        sgemm_nn<<<grid, 256>>>(sc, v, out, SS, DD,
                                (long long)SS * SS, (long long)SS * DD,
                                (long long)SS * DD);
    }
}

// round 3
// speedup vs baseline: 1.6481x; 1.6481x over previous
#include <cuda_runtime.h>
#include <cstdint>

#define BB 32
#define SS 1024
#define II 128
#define HH 128
#define DD 256   // 2*HH

// ---------------- scratch (static device arrays; allocation-free) -------------
__device__ float g_xg[(size_t)2 * BB * SS * 4 * HH];   // [dir][b][s][4H]
__device__ float g_h [(size_t)BB * SS * DD];           // [b][s][2H]
__device__ float g_q [(size_t)BB * SS * DD];
__device__ float g_k [(size_t)BB * SS * DD];
__device__ float g_v [(size_t)BB * SS * DD];           // holds vT: [b][d][t]
__device__ float g_sc[(size_t)BB * SS * SS];           // [b][s][t]

// ============================ mma.sync tf32 GEMM =============================
// C[M,N] = alpha * A[M,K] @ B[N,K]^T (+ b1 + b2), all fp32 I/O, tf32 compute.
// CTA tile 128x128, 8 warps (2M x 4N), warp tile 64x32, mma m16n8k8.
// K % 32 == 0, M % 128 == 0, N % 128 == 0. Batched via blockIdx.z.
// =============================================================================
#define GP 36                       // padded smem row, floats (conflict-free)
#define STG_F (128 * GP)            // floats per operand stage
#define GEMM_SMEM ((4 * STG_F + 128) * 4)

__device__ __forceinline__ uint32_t f2tf(float x) {
    uint32_t r;
    asm("cvt.rna.tf32.f32 %0, %1;" : "=r"(r) : "f"(x));
    return r;
}

__device__ __forceinline__ void mma8(float* d, const uint32_t* a,
                                     const uint32_t* b) {
    asm volatile(
        "mma.sync.aligned.m16n8k8.row.col.f32.tf32.tf32.f32 "
        "{%0,%1,%2,%3}, {%4,%5,%6,%7}, {%8,%9}, {%0,%1,%2,%3};"
        : "+f"(d[0]), "+f"(d[1]), "+f"(d[2]), "+f"(d[3])
        : "r"(a[0]), "r"(a[1]), "r"(a[2]), "r"(a[3]), "r"(b[0]), "r"(b[1]));
}

__global__ __launch_bounds__(256, 1) void mma_gemm_nt(
    const float* __restrict__ A, long long sA,
    const float* __restrict__ B, long long sB,
    float* __restrict__ C, long long sC,
    int K, int N, float alpha,
    const float* __restrict__ b1, const float* __restrict__ b2)
{
    extern __shared__ float sm[];
    float* AsBase = sm;                 // 2 stages of 128*GP
    float* BsBase = sm + 2 * STG_F;     // 2 stages of 128*GP
    float* bias   = sm + 4 * STG_F;     // 128 floats

    const int tid  = threadIdx.x;
    const int wid  = tid >> 5, lane = tid & 31;
    const int wm   = wid >> 2, wn = wid & 3;       // 2 x 4 warp grid
    const int g    = lane >> 2, tg = lane & 3;     // fragment coords

    A += (size_t)blockIdx.z * sA;
    B += (size_t)blockIdx.z * sB;
    C += (size_t)blockIdx.z * sC;
    const int bm = blockIdx.y * 128;
    const int bn = blockIdx.x * 128;

    if (tid < 128) {
        float v = 0.f;
        if (b1) v += b1[bn + tid];
        if (b2) v += b2[bn + tid];
        bias[tid] = v;
    }

    const int lr = tid >> 3;            // 0..31 (rows lr, lr+32, lr+64, lr+96)
    const int c4 = tid & 7;             // float4 index within K-chunk of 32
    const float* Ag0 = A + (size_t)bm * K + c4 * 4;
    const float* Bg0 = B + (size_t)bn * K + c4 * 4;

    float4 ra[4], rb[4];
#define LOADCH(ch) do {                                                      \
        const float* Ac = Ag0 + (ch) * 32;                                   \
        const float* Bc = Bg0 + (ch) * 32;                                   \
        _Pragma("unroll")                                                    \
        for (int i = 0; i < 4; i++) {                                        \
            ra[i] = *(const float4*)(Ac + (size_t)(lr + 32 * i) * K);        \
            rb[i] = *(const float4*)(Bc + (size_t)(lr + 32 * i) * K);        \
        } } while (0)

#define STORECH(st) do {                                                     \
        uint32_t* Aw = (uint32_t*)(AsBase + (st) * STG_F);                   \
        uint32_t* Bw = (uint32_t*)(BsBase + (st) * STG_F);                   \
        _Pragma("unroll")                                                    \
        for (int i = 0; i < 4; i++) {                                        \
            const int o = (lr + 32 * i) * GP + c4 * 4;                       \
            Aw[o + 0] = f2tf(ra[i].x); Aw[o + 1] = f2tf(ra[i].y);            \
            Aw[o + 2] = f2tf(ra[i].z); Aw[o + 3] = f2tf(ra[i].w);            \
            Bw[o + 0] = f2tf(rb[i].x); Bw[o + 1] = f2tf(rb[i].y);            \
            Bw[o + 2] = f2tf(rb[i].z); Bw[o + 3] = f2tf(rb[i].w);            \
        } } while (0)

    float acc[4][4][4];
#pragma unroll
    for (int mt = 0; mt < 4; mt++)
#pragma unroll
        for (int nt = 0; nt < 4; nt++)
#pragma unroll
            for (int e = 0; e < 4; e++) acc[mt][nt][e] = 0.f;

    const int nch = K >> 5;
    LOADCH(0);

    for (int i = 0; i < nch; i++) {
        const int s = i & 1;
        STORECH(s);
        __syncthreads();
        if (i + 1 < nch) LOADCH(i + 1);

        const uint32_t* As = (const uint32_t*)(AsBase + s * STG_F);
        const uint32_t* Bs = (const uint32_t*)(BsBase + s * STG_F);
#pragma unroll
        for (int ks = 0; ks < 4; ks++) {
            uint32_t af[4][4], bf[4][2];
#pragma unroll
            for (int mt = 0; mt < 4; mt++) {
                const int r = (wm * 64 + mt * 16 + g) * GP + ks * 8 + tg;
                af[mt][0] = As[r];
                af[mt][1] = As[r + 8 * GP];
                af[mt][2] = As[r + 4];
                af[mt][3] = As[r + 8 * GP + 4];
            }
#pragma unroll
            for (int nt = 0; nt < 4; nt++) {
                const int r = (wn * 32 + nt * 8 + g) * GP + ks * 8 + tg;
                bf[nt][0] = Bs[r];
                bf[nt][1] = Bs[r + 4];
            }
#pragma unroll
            for (int mt = 0; mt < 4; mt++)
#pragma unroll
                for (int nt = 0; nt < 4; nt++)
                    mma8(acc[mt][nt], af[mt], bf[nt]);
        }
        __syncthreads();
    }

    // epilogue
#pragma unroll
    for (int mt = 0; mt < 4; mt++) {
        const int r0 = bm + wm * 64 + mt * 16 + g;
#pragma unroll
        for (int nt = 0; nt < 4; nt++) {
            const int cl = wn * 32 + nt * 8 + 2 * tg;     // col within tile
            const int c0 = bn + cl;
            float2 o0, o1;
            o0.x = acc[mt][nt][0] * alpha + bias[cl];
            o0.y = acc[mt][nt][1] * alpha + bias[cl + 1];
            o1.x = acc[mt][nt][2] * alpha + bias[cl];
            o1.y = acc[mt][nt][3] * alpha + bias[cl + 1];
            *(float2*)(C + (size_t)r0 * N + c0)       = o0;
            *(float2*)(C + (size_t)(r0 + 8) * N + c0) = o1;
        }
    }
#undef LOADCH
#undef STORECH
}

// =============================================================================
// LSTM recurrence (unchanged from R1, passing): 64 CTAs x 512 threads.
// =============================================================================
#define LSTM_SMEM ((128 + 512) * 4 + 16 * 512 * 8)

__device__ __forceinline__ void fma2(unsigned long long& d,
                                     unsigned long long a,
                                     unsigned long long b)
{
    asm("fma.rn.f32x2 %0, %1, %2, %0;" : "+l"(d) : "l"(a), "l"(b));
}
__device__ __forceinline__ float sum2(unsigned long long a)
{
    return __uint_as_float((unsigned)a) + __uint_as_float((unsigned)(a >> 32));
}

__global__ __launch_bounds__(512) void lstm_kernel(
    const float* __restrict__ xg_all,
    const float* __restrict__ Whh_fw,
    const float* __restrict__ Whh_bw,
    float* __restrict__ Hout)
{
    extern __shared__ float sm[];
    float* h_sh = sm;
    float* gate = sm + 128;
    unsigned long long* w_sh2 = (unsigned long long*)(sm + 640);

    const int dir = blockIdx.x >> 5;
    const int b   = blockIdx.x & 31;
    const int g   = threadIdx.x;
    const float* Whh = dir ? Whh_bw : Whh_fw;

    unsigned long long w2[48];
    {
        const unsigned long long* wr =
            (const unsigned long long*)(Whh + (size_t)g * HH);
#pragma unroll
        for (int i = 0; i < 48; i++) w2[i] = wr[i];
    }
    for (int idx = g; idx < 16 * 512; idx += 512) {
        const int j2 = idx >> 9;
        const int gg = idx & 511;
        w_sh2[idx] =
            *(const unsigned long long*)(Whh + (size_t)gg * HH + 96 + 2 * j2);
    }
    if (g < HH) h_sh[g] = 0.f;
    float c = 0.f;
    __syncthreads();

    const float* xg = xg_all + ((size_t)dir * BB + b) * SS * (4 * HH);

    for (int t = 0; t < SS; t++) {
        const int s = dir ? (SS - 1 - t) : t;
        float acc = xg[(size_t)s * 512 + g];

        unsigned long long a2a = 0ull, a2b = 0ull;
        const ulonglong2* hq = (const ulonglong2*)h_sh;
#pragma unroll
        for (int i = 0; i < 24; i++) {
            ulonglong2 hv = hq[i];
            fma2(a2a, w2[2 * i], hv.x);
            fma2(a2b, w2[2 * i + 1], hv.y);
        }
        const unsigned long long* hp = (const unsigned long long*)h_sh;
#pragma unroll
        for (int j2 = 0; j2 < 16; j2++) {
            unsigned long long wv = w_sh2[j2 * 512 + g];
            if (j2 & 1) fma2(a2b, wv, hp[48 + j2]);
            else        fma2(a2a, wv, hp[48 + j2]);
        }
        acc += sum2(a2a) + sum2(a2b);

        gate[g] = acc;
        __syncthreads();

        if (g < HH) {
            const float i_ = 1.f / (1.f + __expf(-gate[g]));
            const float f_ = 1.f / (1.f + __expf(-gate[HH + g]));
            const float g_ = tanhf(gate[2 * HH + g]);
            const float o_ = 1.f / (1.f + __expf(-gate[3 * HH + g]));
            c = f_ * c + i_ * g_;
            const float h = o_ * tanhf(c);
            h_sh[g] = h;
            Hout[((size_t)b * SS + s) * DD + dir * HH + g] = h;
        }
        __syncthreads();
    }
}

// =============================================================================
// Row softmax (unchanged from R1)
// =============================================================================
__global__ __launch_bounds__(256) void softmax_rows(float* __restrict__ S)
{
    float* row = S + (size_t)blockIdx.x * SS;
    const int t = threadIdx.x;
    __shared__ float red[8];

    float v0 = row[t], v1 = row[t + 256], v2 = row[t + 512], v3 = row[t + 768];

    float m = fmaxf(fmaxf(v0, v1), fmaxf(v2, v3));
#pragma unroll
    for (int o = 16; o > 0; o >>= 1)
        m = fmaxf(m, __shfl_xor_sync(0xffffffffu, m, o));
    if ((t & 31) == 0) red[t >> 5] = m;
    __syncthreads();
    m = fmaxf(fmaxf(fmaxf(red[0], red[1]), fmaxf(red[2], red[3])),
              fmaxf(fmaxf(red[4], red[5]), fmaxf(red[6], red[7])));

    v0 = __expf(v0 - m); v1 = __expf(v1 - m);
    v2 = __expf(v2 - m); v3 = __expf(v3 - m);
    float s = (v0 + v1) + (v2 + v3);
#pragma unroll
    for (int o = 16; o > 0; o >>= 1)
        s += __shfl_xor_sync(0xffffffffu, s, o);
    __syncthreads();
    if ((t & 31) == 0) red[t >> 5] = s;
    __syncthreads();
    s = ((red[0] + red[1]) + (red[2] + red[3])) +
        ((red[4] + red[5]) + (red[6] + red[7]));
    const float inv = 1.f / s;

    row[t]       = v0 * inv;
    row[t + 256] = v1 * inv;
    row[t + 512] = v2 * inv;
    row[t + 768] = v3 * inv;
}

// =============================================================================
// launch
// =============================================================================
extern "C" void kernel_launch(void* const* d_in, const int* in_sizes, int n_in,
                              void* d_out, int out_size)
{
    const float* x     = (const float*)d_in[0];
    const float* fwWih = (const float*)d_in[1];
    const float* fwWhh = (const float*)d_in[2];
    const float* fwbih = (const float*)d_in[3];
    const float* fwbhh = (const float*)d_in[4];
    const float* bwWih = (const float*)d_in[5];
    const float* bwWhh = (const float*)d_in[6];
    const float* bwbih = (const float*)d_in[7];
    const float* bwbhh = (const float*)d_in[8];
    const float* Wq    = (const float*)d_in[9];
    const float* Wk    = (const float*)d_in[10];
    const float* Wv    = (const float*)d_in[11];
    float* out = (float*)d_out;

    float *xg, *h, *q, *k, *v, *sc;
    cudaGetSymbolAddress((void**)&xg, g_xg);
    cudaGetSymbolAddress((void**)&h,  g_h);
    cudaGetSymbolAddress((void**)&q,  g_q);
    cudaGetSymbolAddress((void**)&k,  g_k);
    cudaGetSymbolAddress((void**)&v,  g_v);
    cudaGetSymbolAddress((void**)&sc, g_sc);

    cudaFuncSetAttribute(mma_gemm_nt,
                         cudaFuncAttributeMaxDynamicSharedMemorySize, GEMM_SMEM);
    cudaFuncSetAttribute(lstm_kernel,
                         cudaFuncAttributeMaxDynamicSharedMemorySize, LSTM_SMEM);

    const long long SD  = (long long)SS * DD;
    const long long SS2 = (long long)SS * SS;

    // 1) xg[dir] = x @ Wih^T + bih + bhh   (M=32768, N=512, K=128)
    mma_gemm_nt<<<dim3(4, 256, 1), 256, GEMM_SMEM>>>(
        x, 0, fwWih, 0, xg, 0, II, 4 * HH, 1.f, fwbih, fwbhh);
    mma_gemm_nt<<<dim3(4, 256, 1), 256, GEMM_SMEM>>>(
        x, 0, bwWih, 0, xg + (size_t)BB * SS * 4 * HH, 0, II, 4 * HH, 1.f,
        bwbih, bwbhh);

    // 2) bidirectional LSTM recurrence -> h [B,S,2H]
    lstm_kernel<<<64, 512, LSTM_SMEM>>>(xg, fwWhh, bwWhh, h);

    // 3) q, k projections (M=32768, N=256, K=256)
    mma_gemm_nt<<<dim3(2, 256, 1), 256, GEMM_SMEM>>>(
        h, 0, Wq, 0, q, 0, DD, DD, 1.f, nullptr, nullptr);
    mma_gemm_nt<<<dim3(2, 256, 1), 256, GEMM_SMEM>>>(
        h, 0, Wk, 0, k, 0, DD, DD, 1.f, nullptr, nullptr);

    // 3b) vT[b][d][t] = Wv @ h[b]^T   (M=256, N=1024, K=256, batched)
    mma_gemm_nt<<<dim3(8, 2, 32), 256, GEMM_SMEM>>>(
        Wv, 0, h, SD, v, SD, DD, SS, 1.f, nullptr, nullptr);

    // 4) scores = q @ k^T / 16  (M=1024, N=1024, K=256, batched)
    mma_gemm_nt<<<dim3(8, 8, 32), 256, GEMM_SMEM>>>(
        q, SD, k, SD, sc, SS2, DD, SS, 0.0625f, nullptr, nullptr);

    // 5) softmax over last axis
    softmax_rows<<<BB * SS, 256>>>(sc);

    // 6) out = att @ vT^T  (M=1024, N=256, K=1024, batched)
    mma_gemm_nt<<<dim3(2, 8, 32), 256, GEMM_SMEM>>>(
        sc, SS2, v, SD, out, SD, SS, DD, 1.f, nullptr, nullptr);
}

// round 4
// speedup vs baseline: 1.8044x; 1.0948x over previous
#include <cuda_runtime.h>
#include <cstdint>

#define BB 32
#define SS 1024
#define II 128
#define HH 128
#define DD 256   // 2*HH

// ---------------- scratch (static device arrays; allocation-free) -------------
__device__ float g_xg[(size_t)2 * BB * SS * 4 * HH];   // [dir][b][s][4H]
__device__ float g_h [(size_t)BB * SS * DD];           // [b][s][2H]
__device__ float g_q [(size_t)BB * SS * DD];
__device__ float g_k [(size_t)BB * SS * DD];
__device__ float g_v [(size_t)BB * SS * DD];           // holds vT: [b][d][t]
__device__ float g_sc[(size_t)BB * SS * SS];           // [b][s][t]

// ============================ mma.sync tf32 GEMM =============================
// C[M,N] = alpha * A[M,K] @ B[N,K]^T (+ b1 + b2), fp32 I/O, tf32 compute.
// CTA tile 128x128, 8 warps (2M x 4N), warp tile 64x32, mma m16n8k8.
// 3-stage cp.async pipeline, K chunk = 32. K % 32 == 0, K >= 64.
// =============================================================================
#define GP 36                        // padded smem row (floats); 144B, 16B-aligned
#define STG_F (128 * GP)             // floats per operand stage (18KB)
#define NSTG 3
#define GEMM_SMEM ((2 * NSTG * STG_F + 128) * 4)   // ~111KB

__device__ __forceinline__ uint32_t smem_u32(const void* p) {
    uint32_t a;
    asm("{ .reg .u64 t; cvta.to.shared.u64 t, %1; cvt.u32.u64 %0, t; }"
        : "=r"(a) : "l"(p));
    return a;
}
__device__ __forceinline__ void cp16(uint32_t s, const void* g) {
    asm volatile("cp.async.cg.shared.global [%0], [%1], 16;" :: "r"(s), "l"(g));
}
#define CP_COMMIT() asm volatile("cp.async.commit_group;" ::: "memory")
#define CP_WAIT1()  asm volatile("cp.async.wait_group 1;" ::: "memory")
#define CP_WAIT0()  asm volatile("cp.async.wait_group 0;" ::: "memory")

__device__ __forceinline__ uint32_t f2tf(float x) {
    uint32_t r;
    asm("cvt.rna.tf32.f32 %0, %1;" : "=r"(r) : "f"(x));
    return r;
}

__device__ __forceinline__ void mma8(float* d, const uint32_t* a,
                                     const uint32_t* b) {
    asm volatile(
        "mma.sync.aligned.m16n8k8.row.col.f32.tf32.tf32.f32 "
        "{%0,%1,%2,%3}, {%4,%5,%6,%7}, {%8,%9}, {%0,%1,%2,%3};"
        : "+f"(d[0]), "+f"(d[1]), "+f"(d[2]), "+f"(d[3])
        : "r"(a[0]), "r"(a[1]), "r"(a[2]), "r"(a[3]), "r"(b[0]), "r"(b[1]));
}

__global__ __launch_bounds__(256, 2) void mma_gemm_nt(
    const float* __restrict__ A, long long sA,
    const float* __restrict__ B, long long sB,
    float* __restrict__ C, long long sC,
    int K, int N, float alpha,
    const float* __restrict__ b1, const float* __restrict__ b2)
{
    extern __shared__ float sm[];
    float* AsBase = sm;                       // NSTG stages
    float* BsBase = sm + NSTG * STG_F;        // NSTG stages
    float* bias   = sm + 2 * NSTG * STG_F;    // 128 floats
    const uint32_t smb = smem_u32(sm);

    const int tid  = threadIdx.x;
    const int wid  = tid >> 5, lane = tid & 31;
    const int wm   = wid >> 2, wn = wid & 3;       // 2 x 4 warp grid
    const int g    = lane >> 2, tg = lane & 3;     // fragment coords

    A += (size_t)blockIdx.z * sA;
    B += (size_t)blockIdx.z * sB;
    C += (size_t)blockIdx.z * sC;
    const int bm = blockIdx.y * 128;
    const int bn = blockIdx.x * 128;

    if (tid < 128) {
        float v = 0.f;
        if (b1) v += b1[bn + tid];
        if (b2) v += b2[bn + tid];
        bias[tid] = v;
    }

    const int lr = tid >> 3;            // 0..31 (rows lr, lr+32, lr+64, lr+96)
    const int c4 = tid & 7;             // float4 index within K-chunk of 32
    const float* Ag0 = A + (size_t)bm * K + c4 * 4;
    const float* Bg0 = B + (size_t)bn * K + c4 * 4;

#define LOADCH(ch, st) do {                                                  \
        const uint32_t abase = smb + (uint32_t)(st) * (STG_F * 4);           \
        const uint32_t bbase = smb + (uint32_t)(NSTG + (st)) * (STG_F * 4);  \
        const float* Ac = Ag0 + (ch) * 32;                                   \
        const float* Bc = Bg0 + (ch) * 32;                                   \
        _Pragma("unroll")                                                    \
        for (int i = 0; i < 4; i++) {                                        \
            const int row = lr + 32 * i;                                     \
            const uint32_t off = (uint32_t)(row * GP + c4 * 4) * 4;          \
            cp16(abase + off, Ac + (size_t)row * K);                         \
            cp16(bbase + off, Bc + (size_t)row * K);                         \
        } } while (0)

    float acc[4][4][4];
#pragma unroll
    for (int mt = 0; mt < 4; mt++)
#pragma unroll
        for (int nt = 0; nt < 4; nt++)
#pragma unroll
            for (int e = 0; e < 4; e++) acc[mt][nt][e] = 0.f;

    const int nch = K >> 5;
    LOADCH(0, 0); CP_COMMIT();
    LOADCH(1, 1); CP_COMMIT();

    for (int i = 0; i < nch; i++) {
        const int s = i % 3;
        if (i + 2 < nch) CP_WAIT1(); else CP_WAIT0();
        __syncthreads();
        if (i + 2 < nch) { LOADCH(i + 2, (i + 2) % 3); CP_COMMIT(); }

        const float* As = AsBase + s * STG_F;
        const float* Bs = BsBase + s * STG_F;
#pragma unroll
        for (int ks = 0; ks < 4; ks++) {
            uint32_t af[4][4], bf[4][2];
#pragma unroll
            for (int mt = 0; mt < 4; mt++) {
                const int r = (wm * 64 + mt * 16 + g) * GP + ks * 8 + tg;
                af[mt][0] = f2tf(As[r]);
                af[mt][1] = f2tf(As[r + 8 * GP]);
                af[mt][2] = f2tf(As[r + 4]);
                af[mt][3] = f2tf(As[r + 8 * GP + 4]);
            }
#pragma unroll
            for (int nt = 0; nt < 4; nt++) {
                const int r = (wn * 32 + nt * 8 + g) * GP + ks * 8 + tg;
                bf[nt][0] = f2tf(Bs[r]);
                bf[nt][1] = f2tf(Bs[r + 4]);
            }
#pragma unroll
            for (int mt = 0; mt < 4; mt++)
#pragma unroll
                for (int nt = 0; nt < 4; nt++)
                    mma8(acc[mt][nt], af[mt], bf[nt]);
        }
    }
    __syncthreads();

    // epilogue
#pragma unroll
    for (int mt = 0; mt < 4; mt++) {
        const int r0 = bm + wm * 64 + mt * 16 + g;
#pragma unroll
        for (int nt = 0; nt < 4; nt++) {
            const int cl = wn * 32 + nt * 8 + 2 * tg;
            const int c0 = bn + cl;
            float2 o0, o1;
            o0.x = acc[mt][nt][0] * alpha + bias[cl];
            o0.y = acc[mt][nt][1] * alpha + bias[cl + 1];
            o1.x = acc[mt][nt][2] * alpha + bias[cl];
            o1.y = acc[mt][nt][3] * alpha + bias[cl + 1];
            *(float2*)(C + (size_t)r0 * N + c0)       = o0;
            *(float2*)(C + (size_t)(r0 + 8) * N + c0) = o1;
        }
    }
#undef LOADCH
}

// =============================================================================
// LSTM recurrence: 64 CTAs x 512 threads, reg+smem Whh, xg prefetch.
// =============================================================================
#define LSTM_SMEM ((128 + 512) * 4 + 16 * 512 * 8)

__device__ __forceinline__ void fma2(unsigned long long& d,
                                     unsigned long long a,
                                     unsigned long long b)
{
    asm("fma.rn.f32x2 %0, %1, %2, %0;" : "+l"(d) : "l"(a), "l"(b));
}
__device__ __forceinline__ float sum2(unsigned long long a)
{
    return __uint_as_float((unsigned)a) + __uint_as_float((unsigned)(a >> 32));
}

__global__ __launch_bounds__(512) void lstm_kernel(
    const float* __restrict__ xg_all,
    const float* __restrict__ Whh_fw,
    const float* __restrict__ Whh_bw,
    float* __restrict__ Hout)
{
    extern __shared__ float sm[];
    float* h_sh = sm;
    float* gate = sm + 128;
    unsigned long long* w_sh2 = (unsigned long long*)(sm + 640);

    const int dir = blockIdx.x >> 5;
    const int b   = blockIdx.x & 31;
    const int g   = threadIdx.x;
    const float* Whh = dir ? Whh_bw : Whh_fw;

    unsigned long long w2[48];
    {
        const unsigned long long* wr =
            (const unsigned long long*)(Whh + (size_t)g * HH);
#pragma unroll
        for (int i = 0; i < 48; i++) w2[i] = wr[i];
    }
    for (int idx = g; idx < 16 * 512; idx += 512) {
        const int j2 = idx >> 9;
        const int gg = idx & 511;
        w_sh2[idx] =
            *(const unsigned long long*)(Whh + (size_t)gg * HH + 96 + 2 * j2);
    }
    if (g < HH) h_sh[g] = 0.f;
    float c = 0.f;
    __syncthreads();

    const float* xg = xg_all + ((size_t)dir * BB + b) * SS * (4 * HH);

    // prefetch step 0's xg
    float xg_cur = __ldcs(xg + (size_t)(dir ? SS - 1 : 0) * 512 + g);

    for (int t = 0; t < SS; t++) {
        const int s = dir ? (SS - 1 - t) : t;
        float acc = xg_cur;
        if (t + 1 < SS) {
            const int sn = dir ? (SS - 2 - t) : (t + 1);
            xg_cur = __ldcs(xg + (size_t)sn * 512 + g);   // overlaps fma work
        }

        unsigned long long a2a = 0ull, a2b = 0ull;
        const ulonglong2* hq = (const ulonglong2*)h_sh;
#pragma unroll
        for (int i = 0; i < 24; i++) {
            ulonglong2 hv = hq[i];
            fma2(a2a, w2[2 * i], hv.x);
            fma2(a2b, w2[2 * i + 1], hv.y);
        }
        const unsigned long long* hp = (const unsigned long long*)h_sh;
#pragma unroll
        for (int j2 = 0; j2 < 16; j2++) {
            unsigned long long wv = w_sh2[j2 * 512 + g];
            if (j2 & 1) fma2(a2b, wv, hp[48 + j2]);
            else        fma2(a2a, wv, hp[48 + j2]);
        }
        acc += sum2(a2a) + sum2(a2b);

        gate[g] = acc;
        __syncthreads();

        if (g < HH) {
            const float i_ = 1.f / (1.f + __expf(-gate[g]));
            const float f_ = 1.f / (1.f + __expf(-gate[HH + g]));
            const float g_ = tanhf(gate[2 * HH + g]);
            const float o_ = 1.f / (1.f + __expf(-gate[3 * HH + g]));
            c = f_ * c + i_ * g_;
            const float h = o_ * tanhf(c);
            h_sh[g] = h;
            Hout[((size_t)b * SS + s) * DD + dir * HH + g] = h;
        }
        __syncthreads();
    }
}

// =============================================================================
// Row softmax
// =============================================================================
__global__ __launch_bounds__(256) void softmax_rows(float* __restrict__ S)
{
    float* row = S + (size_t)blockIdx.x * SS;
    const int t = threadIdx.x;
    __shared__ float red[8];

    float v0 = row[t], v1 = row[t + 256], v2 = row[t + 512], v3 = row[t + 768];

    float m = fmaxf(fmaxf(v0, v1), fmaxf(v2, v3));
#pragma unroll
    for (int o = 16; o > 0; o >>= 1)
        m = fmaxf(m, __shfl_xor_sync(0xffffffffu, m, o));
    if ((t & 31) == 0) red[t >> 5] = m;
    __syncthreads();
    m = fmaxf(fmaxf(fmaxf(red[0], red[1]), fmaxf(red[2], red[3])),
              fmaxf(fmaxf(red[4], red[5]), fmaxf(red[6], red[7])));

    v0 = __expf(v0 - m); v1 = __expf(v1 - m);
    v2 = __expf(v2 - m); v3 = __expf(v3 - m);
    float s = (v0 + v1) + (v2 + v3);
#pragma unroll
    for (int o = 16; o > 0; o >>= 1)
        s += __shfl_xor_sync(0xffffffffu, s, o);
    __syncthreads();
    if ((t & 31) == 0) red[t >> 5] = s;
    __syncthreads();
    s = ((red[0] + red[1]) + (red[2] + red[3])) +
        ((red[4] + red[5]) + (red[6] + red[7]));
    const float inv = 1.f / s;

    row[t]       = v0 * inv;
    row[t + 256] = v1 * inv;
    row[t + 512] = v2 * inv;
    row[t + 768] = v3 * inv;
}

// =============================================================================
// launch
// =============================================================================
extern "C" void kernel_launch(void* const* d_in, const int* in_sizes, int n_in,
                              void* d_out, int out_size)
{
    const float* x     = (const float*)d_in[0];
    const float* fwWih = (const float*)d_in[1];
    const float* fwWhh = (const float*)d_in[2];
    const float* fwbih = (const float*)d_in[3];
    const float* fwbhh = (const float*)d_in[4];
    const float* bwWih = (const float*)d_in[5];
    const float* bwWhh = (const float*)d_in[6];
    const float* bwbih = (const float*)d_in[7];
    const float* bwbhh = (const float*)d_in[8];
    const float* Wq    = (const float*)d_in[9];
    const float* Wk    = (const float*)d_in[10];
    const float* Wv    = (const float*)d_in[11];
    float* out = (float*)d_out;

    float *xg, *h, *q, *k, *v, *sc;
    cudaGetSymbolAddress((void**)&xg, g_xg);
    cudaGetSymbolAddress((void**)&h,  g_h);
    cudaGetSymbolAddress((void**)&q,  g_q);
    cudaGetSymbolAddress((void**)&k,  g_k);
    cudaGetSymbolAddress((void**)&v,  g_v);
    cudaGetSymbolAddress((void**)&sc, g_sc);

    cudaFuncSetAttribute(mma_gemm_nt,
                         cudaFuncAttributeMaxDynamicSharedMemorySize, GEMM_SMEM);
    cudaFuncSetAttribute(lstm_kernel,
                         cudaFuncAttributeMaxDynamicSharedMemorySize, LSTM_SMEM);

    const long long SD  = (long long)SS * DD;
    const long long SS2 = (long long)SS * SS;

    // 1) xg[dir] = x @ Wih^T + bih + bhh   (M=32768, N=512, K=128)
    mma_gemm_nt<<<dim3(4, 256, 1), 256, GEMM_SMEM>>>(
        x, 0, fwWih, 0, xg, 0, II, 4 * HH, 1.f, fwbih, fwbhh);
    mma_gemm_nt<<<dim3(4, 256, 1), 256, GEMM_SMEM>>>(
        x, 0, bwWih, 0, xg + (size_t)BB * SS * 4 * HH, 0, II, 4 * HH, 1.f,
        bwbih, bwbhh);

    // 2) bidirectional LSTM recurrence -> h [B,S,2H]
    lstm_kernel<<<64, 512, LSTM_SMEM>>>(xg, fwWhh, bwWhh, h);

    // 3) q, k projections (M=32768, N=256, K=256)
    mma_gemm_nt<<<dim3(2, 256, 1), 256, GEMM_SMEM>>>(
        h, 0, Wq, 0, q, 0, DD, DD, 1.f, nullptr, nullptr);
    mma_gemm_nt<<<dim3(2, 256, 1), 256, GEMM_SMEM>>>(
        h, 0, Wk, 0, k, 0, DD, DD, 1.f, nullptr, nullptr);

    // 3b) vT[b][d][t] = Wv @ h[b]^T   (M=256, N=1024, K=256, batched)
    mma_gemm_nt<<<dim3(8, 2, 32), 256, GEMM_SMEM>>>(
        Wv, 0, h, SD, v, SD, DD, SS, 1.f, nullptr, nullptr);

    // 4) scores = q @ k^T / 16  (M=1024, N=1024, K=256, batched)
    mma_gemm_nt<<<dim3(8, 8, 32), 256, GEMM_SMEM>>>(
        q, SD, k, SD, sc, SS2, DD, SS, 0.0625f, nullptr, nullptr);

    // 5) softmax over last axis
    softmax_rows<<<BB * SS, 256>>>(sc);

    // 6) out = att @ vT^T  (M=1024, N=256, K=1024, batched)
    mma_gemm_nt<<<dim3(2, 8, 32), 256, GEMM_SMEM>>>(
        sc, SS2, v, SD, out, SD, SS, DD, 1.f, nullptr, nullptr);
}

// round 6
// speedup vs baseline: 1.8386x; 1.0189x over previous
#include <cuda_runtime.h>
#include <cstdint>

#define BB 32
#define SS 1024
#define II 128
#define HH 128
#define DD 256   // 2*HH

// ---------------- scratch (static device arrays; allocation-free) -------------
__device__ float g_xg[(size_t)2 * BB * SS * 4 * HH];   // [dir][b][s][4H]
__device__ float g_h [(size_t)BB * SS * DD];           // [b][s][2H] (tf32-rounded)
__device__ float g_q [(size_t)BB * SS * DD];           // tf32-rounded
__device__ float g_k [(size_t)BB * SS * DD];           // tf32-rounded
__device__ float g_v [(size_t)BB * SS * DD];           // vT [b][d][t], tf32-rounded
__device__ float g_sc[(size_t)BB * SS * SS];           // [b][s][t]

// ============================ mma.sync tf32 GEMM =============================
// C[M,N] = alpha * A[M,K] @ B[N,K]^T (+ b1 + b2), fp32 I/O, tf32 compute.
// CTA tile 128x128, 8 warps (2M x 4N), warp tile 64x32, mma m16n8k8.
// 3-stage cp.async pipeline, K chunk = 32. K % 32 == 0, K >= 64.
// cvtA/cvtB: operand needs tf32 rounding (else already rounded by producer).
// roundC: round output to tf32 (for GEMM-consumed products).
// =============================================================================
#define GP 36                        // padded smem row (floats)
#define STG_F (128 * GP)
#define NSTG 3
#define GEMM_SMEM ((2 * NSTG * STG_F + 128) * 4)   // ~111KB

__device__ __forceinline__ uint32_t smem_u32(const void* p) {
    uint32_t a;
    asm("{ .reg .u64 t; cvta.to.shared.u64 t, %1; cvt.u32.u64 %0, t; }"
        : "=r"(a) : "l"(p));
    return a;
}
__device__ __forceinline__ void cp16(uint32_t s, const void* g) {
    asm volatile("cp.async.cg.shared.global [%0], [%1], 16;" :: "r"(s), "l"(g));
}
#define CP_COMMIT() asm volatile("cp.async.commit_group;" ::: "memory")
#define CP_WAIT1()  asm volatile("cp.async.wait_group 1;" ::: "memory")
#define CP_WAIT0()  asm volatile("cp.async.wait_group 0;" ::: "memory")

__device__ __forceinline__ uint32_t f2tf(float x) {
    uint32_t r;
    asm("cvt.rna.tf32.f32 %0, %1;" : "=r"(r) : "f"(x));
    return r;
}
__device__ __forceinline__ float roundtf(float x) {
    return __uint_as_float(f2tf(x));
}

__device__ __forceinline__ void mma8(float* d, const uint32_t* a,
                                     const uint32_t* b) {
    asm volatile(
        "mma.sync.aligned.m16n8k8.row.col.f32.tf32.tf32.f32 "
        "{%0,%1,%2,%3}, {%4,%5,%6,%7}, {%8,%9}, {%0,%1,%2,%3};"
        : "+f"(d[0]), "+f"(d[1]), "+f"(d[2]), "+f"(d[3])
        : "r"(a[0]), "r"(a[1]), "r"(a[2]), "r"(a[3]), "r"(b[0]), "r"(b[1]));
}

template <bool CVTA, bool CVTB, bool ROUNDC>
__global__ __launch_bounds__(256, 2) void mma_gemm_nt(
    const float* __restrict__ A, long long sA,
    const float* __restrict__ B, long long sB,
    float* __restrict__ C, long long sC,
    int K, int N, float alpha,
    const float* __restrict__ b1, const float* __restrict__ b2)
{
    extern __shared__ float sm[];
    float* AsBase = sm;
    float* BsBase = sm + NSTG * STG_F;
    float* bias   = sm + 2 * NSTG * STG_F;
    const uint32_t smb = smem_u32(sm);

    const int tid  = threadIdx.x;
    const int wid  = tid >> 5, lane = tid & 31;
    const int wm   = wid >> 2, wn = wid & 3;
    const int g    = lane >> 2, tg = lane & 3;

    A += (size_t)blockIdx.z * sA;
    B += (size_t)blockIdx.z * sB;
    C += (size_t)blockIdx.z * sC;
    const int bm = blockIdx.y * 128;
    const int bn = blockIdx.x * 128;

    if (tid < 128) {
        float v = 0.f;
        if (b1) v += b1[bn + tid];
        if (b2) v += b2[bn + tid];
        bias[tid] = v;
    }

    const int lr = tid >> 3;
    const int c4 = tid & 7;
    const float* Ag0 = A + (size_t)bm * K + c4 * 4;
    const float* Bg0 = B + (size_t)bn * K + c4 * 4;

#define LOADCH(ch, st) do {                                                  \
        const uint32_t abase = smb + (uint32_t)(st) * (STG_F * 4);           \
        const uint32_t bbase = smb + (uint32_t)(NSTG + (st)) * (STG_F * 4);  \
        const float* Ac = Ag0 + (ch) * 32;                                   \
        const float* Bc = Bg0 + (ch) * 32;                                   \
        _Pragma("unroll")                                                    \
        for (int i = 0; i < 4; i++) {                                        \
            const int row = lr + 32 * i;                                     \
            const uint32_t off = (uint32_t)(row * GP + c4 * 4) * 4;          \
            cp16(abase + off, Ac + (size_t)row * K);                         \
            cp16(bbase + off, Bc + (size_t)row * K);                         \
        } } while (0)

    float acc[4][4][4];
#pragma unroll
    for (int mt = 0; mt < 4; mt++)
#pragma unroll
        for (int nt = 0; nt < 4; nt++)
#pragma unroll
            for (int e = 0; e < 4; e++) acc[mt][nt][e] = 0.f;

    const int nch = K >> 5;
    LOADCH(0, 0); CP_COMMIT();
    LOADCH(1, 1); CP_COMMIT();

    for (int i = 0; i < nch; i++) {
        const int s = i % 3;
        if (i + 2 < nch) CP_WAIT1(); else CP_WAIT0();
        __syncthreads();
        if (i + 2 < nch) { LOADCH(i + 2, (i + 2) % 3); CP_COMMIT(); }

        const float* As = AsBase + s * STG_F;
        const float* Bs = BsBase + s * STG_F;
        const uint32_t* Asu = (const uint32_t*)As;
        const uint32_t* Bsu = (const uint32_t*)Bs;
#pragma unroll
        for (int ks = 0; ks < 4; ks++) {
            uint32_t af[4][4], bf[4][2];
#pragma unroll
            for (int mt = 0; mt < 4; mt++) {
                const int r = (wm * 64 + mt * 16 + g) * GP + ks * 8 + tg;
                if (CVTA) {
                    af[mt][0] = f2tf(As[r]);
                    af[mt][1] = f2tf(As[r + 8 * GP]);
                    af[mt][2] = f2tf(As[r + 4]);
                    af[mt][3] = f2tf(As[r + 8 * GP + 4]);
                } else {
                    af[mt][0] = Asu[r];
                    af[mt][1] = Asu[r + 8 * GP];
                    af[mt][2] = Asu[r + 4];
                    af[mt][3] = Asu[r + 8 * GP + 4];
                }
            }
#pragma unroll
            for (int nt = 0; nt < 4; nt++) {
                const int r = (wn * 32 + nt * 8 + g) * GP + ks * 8 + tg;
                if (CVTB) {
                    bf[nt][0] = f2tf(Bs[r]);
                    bf[nt][1] = f2tf(Bs[r + 4]);
                } else {
                    bf[nt][0] = Bsu[r];
                    bf[nt][1] = Bsu[r + 4];
                }
            }
#pragma unroll
            for (int mt = 0; mt < 4; mt++)
#pragma unroll
                for (int nt = 0; nt < 4; nt++)
                    mma8(acc[mt][nt], af[mt], bf[nt]);
        }
    }
    __syncthreads();

    // epilogue
#pragma unroll
    for (int mt = 0; mt < 4; mt++) {
        const int r0 = bm + wm * 64 + mt * 16 + g;
#pragma unroll
        for (int nt = 0; nt < 4; nt++) {
            const int cl = wn * 32 + nt * 8 + 2 * tg;
            const int c0 = bn + cl;
            float2 o0, o1;
            o0.x = acc[mt][nt][0] * alpha + bias[cl];
            o0.y = acc[mt][nt][1] * alpha + bias[cl + 1];
            o1.x = acc[mt][nt][2] * alpha + bias[cl];
            o1.y = acc[mt][nt][3] * alpha + bias[cl + 1];
            if (ROUNDC) {
                o0.x = roundtf(o0.x); o0.y = roundtf(o0.y);
                o1.x = roundtf(o1.x); o1.y = roundtf(o1.y);
            }
            *(float2*)(C + (size_t)r0 * N + c0)       = o0;
            *(float2*)(C + (size_t)(r0 + 8) * N + c0) = o1;
        }
    }
#undef LOADCH
}

// =============================================================================
// LSTM recurrence: 64 CTAs x 512 threads, reg+smem Whh, xg prefetch.
// Hout is stored tf32-rounded (consumed only by GEMMs); recurrence stays fp32.
// =============================================================================
#define LSTM_SMEM ((128 + 512) * 4 + 16 * 512 * 8)

__device__ __forceinline__ void fma2(unsigned long long& d,
                                     unsigned long long a,
                                     unsigned long long b)
{
    asm("fma.rn.f32x2 %0, %1, %2, %0;" : "+l"(d) : "l"(a), "l"(b));
}
__device__ __forceinline__ float sum2(unsigned long long a)
{
    return __uint_as_float((unsigned)a) + __uint_as_float((unsigned)(a >> 32));
}

__global__ __launch_bounds__(512) void lstm_kernel(
    const float* __restrict__ xg_all,
    const float* __restrict__ Whh_fw,
    const float* __restrict__ Whh_bw,
    float* __restrict__ Hout)
{
    extern __shared__ float sm[];
    float* h_sh = sm;
    float* gate = sm + 128;
    unsigned long long* w_sh2 = (unsigned long long*)(sm + 640);

    const int dir = blockIdx.x >> 5;
    const int b   = blockIdx.x & 31;
    const int g   = threadIdx.x;
    const float* Whh = dir ? Whh_bw : Whh_fw;

    unsigned long long w2[48];
    {
        const unsigned long long* wr =
            (const unsigned long long*)(Whh + (size_t)g * HH);
#pragma unroll
        for (int i = 0; i < 48; i++) w2[i] = wr[i];
    }
    for (int idx = g; idx < 16 * 512; idx += 512) {
        const int j2 = idx >> 9;
        const int gg = idx & 511;
        w_sh2[idx] =
            *(const unsigned long long*)(Whh + (size_t)gg * HH + 96 + 2 * j2);
    }
    if (g < HH) h_sh[g] = 0.f;
    float c = 0.f;
    __syncthreads();

    const float* xg = xg_all + ((size_t)dir * BB + b) * SS * (4 * HH);

    float xg_cur = __ldcs(xg + (size_t)(dir ? SS - 1 : 0) * 512 + g);

    for (int t = 0; t < SS; t++) {
        const int s = dir ? (SS - 1 - t) : t;
        float acc = xg_cur;
        if (t + 1 < SS) {
            const int sn = dir ? (SS - 2 - t) : (t + 1);
            xg_cur = __ldcs(xg + (size_t)sn * 512 + g);
        }

        unsigned long long a2a = 0ull, a2b = 0ull;
        const ulonglong2* hq = (const ulonglong2*)h_sh;
#pragma unroll
        for (int i = 0; i < 24; i++) {
            ulonglong2 hv = hq[i];
            fma2(a2a, w2[2 * i], hv.x);
            fma2(a2b, w2[2 * i + 1], hv.y);
        }
        const unsigned long long* hp = (const unsigned long long*)h_sh;
#pragma unroll
        for (int j2 = 0; j2 < 16; j2++) {
            unsigned long long wv = w_sh2[j2 * 512 + g];
            if (j2 & 1) fma2(a2b, wv, hp[48 + j2]);
            else        fma2(a2a, wv, hp[48 + j2]);
        }
        acc += sum2(a2a) + sum2(a2b);

        gate[g] = acc;
        __syncthreads();

        if (g < HH) {
            const float i_ = 1.f / (1.f + __expf(-gate[g]));
            const float f_ = 1.f / (1.f + __expf(-gate[HH + g]));
            const float g_ = tanhf(gate[2 * HH + g]);
            const float o_ = 1.f / (1.f + __expf(-gate[3 * HH + g]));
            c = f_ * c + i_ * g_;
            const float h = o_ * tanhf(c);
            h_sh[g] = h;                     // full precision for recurrence
            Hout[((size_t)b * SS + s) * DD + dir * HH + g] = roundtf(h);
        }
        __syncthreads();
    }
}

// =============================================================================
// Row softmax; output tf32-rounded (consumed only by att@v GEMM)
// =============================================================================
__global__ __launch_bounds__(256) void softmax_rows(float* __restrict__ S)
{
    float* row = S + (size_t)blockIdx.x * SS;
    const int t = threadIdx.x;
    __shared__ float red[8];

    float v0 = row[t], v1 = row[t + 256], v2 = row[t + 512], v3 = row[t + 768];

    float m = fmaxf(fmaxf(v0, v1), fmaxf(v2, v3));
#pragma unroll
    for (int o = 16; o > 0; o >>= 1)
        m = fmaxf(m, __shfl_xor_sync(0xffffffffu, m, o));
    if ((t & 31) == 0) red[t >> 5] = m;
    __syncthreads();
    m = fmaxf(fmaxf(fmaxf(red[0], red[1]), fmaxf(red[2], red[3])),
              fmaxf(fmaxf(red[4], red[5]), fmaxf(red[6], red[7])));

    v0 = __expf(v0 - m); v1 = __expf(v1 - m);
    v2 = __expf(v2 - m); v3 = __expf(v3 - m);
    float s = (v0 + v1) + (v2 + v3);
#pragma unroll
    for (int o = 16; o > 0; o >>= 1)
        s += __shfl_xor_sync(0xffffffffu, s, o);
    __syncthreads();
    if ((t & 31) == 0) red[t >> 5] = s;
    __syncthreads();
    s = ((red[0] + red[1]) + (red[2] + red[3])) +
        ((red[4] + red[5]) + (red[6] + red[7]));
    const float inv = 1.f / s;

    row[t]       = roundtf(v0 * inv);
    row[t + 256] = roundtf(v1 * inv);
    row[t + 512] = roundtf(v2 * inv);
    row[t + 768] = roundtf(v3 * inv);
}

// =============================================================================
// launch
// =============================================================================
extern "C" void kernel_launch(void* const* d_in, const int* in_sizes, int n_in,
                              void* d_out, int out_size)
{
    const float* x     = (const float*)d_in[0];
    const float* fwWih = (const float*)d_in[1];
    const float* fwWhh = (const float*)d_in[2];
    const float* fwbih = (const float*)d_in[3];
    const float* fwbhh = (const float*)d_in[4];
    const float* bwWih = (const float*)d_in[5];
    const float* bwWhh = (const float*)d_in[6];
    const float* bwbih = (const float*)d_in[7];
    const float* bwbhh = (const float*)d_in[8];
    const float* Wq    = (const float*)d_in[9];
    const float* Wk    = (const float*)d_in[10];
    const float* Wv    = (const float*)d_in[11];
    float* out = (float*)d_out;

    float *xg, *h, *q, *k, *v, *sc;
    cudaGetSymbolAddress((void**)&xg, g_xg);
    cudaGetSymbolAddress((void**)&h,  g_h);
    cudaGetSymbolAddress((void**)&q,  g_q);
    cudaGetSymbolAddress((void**)&k,  g_k);
    cudaGetSymbolAddress((void**)&v,  g_v);
    cudaGetSymbolAddress((void**)&sc, g_sc);

    // NB: every template instantiation is a distinct kernel — each launched
    // variant MUST get the dynamic-smem opt-in (R5 missed <true,false,true>).
    cudaFuncSetAttribute(mma_gemm_nt<true, true, false>,
                         cudaFuncAttributeMaxDynamicSharedMemorySize, GEMM_SMEM);
    cudaFuncSetAttribute(mma_gemm_nt<false, true, true>,
                         cudaFuncAttributeMaxDynamicSharedMemorySize, GEMM_SMEM);
    cudaFuncSetAttribute(mma_gemm_nt<true, false, true>,
                         cudaFuncAttributeMaxDynamicSharedMemorySize, GEMM_SMEM);
    cudaFuncSetAttribute(mma_gemm_nt<false, false, false>,
                         cudaFuncAttributeMaxDynamicSharedMemorySize, GEMM_SMEM);
    cudaFuncSetAttribute(lstm_kernel,
                         cudaFuncAttributeMaxDynamicSharedMemorySize, LSTM_SMEM);

    const long long SD  = (long long)SS * DD;
    const long long SS2 = (long long)SS * SS;

    // 1) xg[dir] = x @ Wih^T + bih + bhh  (raw inputs: cvt both; C full-precision)
    mma_gemm_nt<true, true, false><<<dim3(4, 256, 1), 256, GEMM_SMEM>>>(
        x, 0, fwWih, 0, xg, 0, II, 4 * HH, 1.f, fwbih, fwbhh);
    mma_gemm_nt<true, true, false><<<dim3(4, 256, 1), 256, GEMM_SMEM>>>(
        x, 0, bwWih, 0, xg + (size_t)BB * SS * 4 * HH, 0, II, 4 * HH, 1.f,
        bwbih, bwbhh);

    // 2) bidirectional LSTM recurrence -> h [B,S,2H] (rounded)
    lstm_kernel<<<64, 512, LSTM_SMEM>>>(xg, fwWhh, bwWhh, h);

    // 3) q, k projections: A=h pre-rounded, B=W raw; round C
    mma_gemm_nt<false, true, true><<<dim3(2, 256, 1), 256, GEMM_SMEM>>>(
        h, 0, Wq, 0, q, 0, DD, DD, 1.f, nullptr, nullptr);
    mma_gemm_nt<false, true, true><<<dim3(2, 256, 1), 256, GEMM_SMEM>>>(
        h, 0, Wk, 0, k, 0, DD, DD, 1.f, nullptr, nullptr);

    // 3b) vT[b][d][t] = Wv @ h[b]^T: cvtA for Wv, B=h pre-rounded; round C
    mma_gemm_nt<true, false, true><<<dim3(8, 2, 32), 256, GEMM_SMEM>>>(
        Wv, 0, h, SD, v, SD, DD, SS, 1.f, nullptr, nullptr);

    // 4) scores = q @ k^T / 16: both pre-rounded, no cvt; C full-precision
    mma_gemm_nt<false, false, false><<<dim3(8, 8, 32), 256, GEMM_SMEM>>>(
        q, SD, k, SD, sc, SS2, DD, SS, 0.0625f, nullptr, nullptr);

    // 5) softmax (rounds output)
    softmax_rows<<<BB * SS, 256>>>(sc);

    // 6) out = att @ vT^T: both pre-rounded, no cvt
    mma_gemm_nt<false, false, false><<<dim3(2, 8, 32), 256, GEMM_SMEM>>>(
        sc, SS2, v, SD, out, SD, SS, DD, 1.f, nullptr, nullptr);
}

// round 7
// speedup vs baseline: 1.9294x; 1.0494x over previous
#include <cuda_runtime.h>
#include <cstdint>

#define BB 32
#define SS 1024
#define II 128
#define HH 128
#define DD 256   // 2*HH

// ---------------- scratch (static device arrays; allocation-free) -------------
__device__ float g_xg[(size_t)2 * BB * SS * 4 * HH];   // [dir][b][s][4H]
__device__ float g_h [(size_t)BB * SS * DD];           // [b][s][2H] (tf32-rounded)
__device__ float g_qk[(size_t)2 * BB * SS * DD];       // q then k, tf32-rounded
__device__ float g_v [(size_t)BB * SS * DD];           // vT [b][d][t], tf32-rounded
__device__ float g_sc[(size_t)BB * SS * SS];           // [b][s][t]
// staged weights for merged launches
__device__ float g_wqk[(size_t)2 * DD * DD];           // Wq ; Wk
__device__ float g_wih[(size_t)2 * 4 * HH * II];       // fwWih ; bwWih
__device__ float g_b1 [2 * 4 * HH];                    // fwbih ; bwbih
__device__ float g_b2 [2 * 4 * HH];                    // fwbhh ; bwbhh

// ============================ mma.sync tf32 GEMM =============================
// C[M,N] = alpha * A[M,K] @ B[N,K]^T (+ b1 + b2), fp32 I/O, tf32 compute.
// CTA tile 128x128, 8 warps (2M x 4N), warp tile 64x32, mma m16n8k8.
// 3-stage cp.async pipeline, K chunk = 32. K % 32 == 0, K >= 64.
// =============================================================================
#define GP 36
#define STG_F (128 * GP)
#define NSTG 3
#define GEMM_SMEM ((2 * NSTG * STG_F + 128) * 4)   // ~111KB

__device__ __forceinline__ uint32_t smem_u32(const void* p) {
    uint32_t a;
    asm("{ .reg .u64 t; cvta.to.shared.u64 t, %1; cvt.u32.u64 %0, t; }"
        : "=r"(a) : "l"(p));
    return a;
}
__device__ __forceinline__ void cp16(uint32_t s, const void* g) {
    asm volatile("cp.async.cg.shared.global [%0], [%1], 16;" :: "r"(s), "l"(g));
}
#define CP_COMMIT() asm volatile("cp.async.commit_group;" ::: "memory")
#define CP_WAIT1()  asm volatile("cp.async.wait_group 1;" ::: "memory")
#define CP_WAIT0()  asm volatile("cp.async.wait_group 0;" ::: "memory")

__device__ __forceinline__ uint32_t f2tf(float x) {
    uint32_t r;
    asm("cvt.rna.tf32.f32 %0, %1;" : "=r"(r) : "f"(x));
    return r;
}
__device__ __forceinline__ float roundtf(float x) {
    return __uint_as_float(f2tf(x));
}

__device__ __forceinline__ void mma8(float* d, const uint32_t* a,
                                     const uint32_t* b) {
    asm volatile(
        "mma.sync.aligned.m16n8k8.row.col.f32.tf32.tf32.f32 "
        "{%0,%1,%2,%3}, {%4,%5,%6,%7}, {%8,%9}, {%0,%1,%2,%3};"
        : "+f"(d[0]), "+f"(d[1]), "+f"(d[2]), "+f"(d[3])
        : "r"(a[0]), "r"(a[1]), "r"(a[2]), "r"(a[3]), "r"(b[0]), "r"(b[1]));
}

template <bool CVTA, bool CVTB, bool ROUNDC>
__global__ __launch_bounds__(256, 2) void mma_gemm_nt(
    const float* __restrict__ A, long long sA,
    const float* __restrict__ B, long long sB,
    float* __restrict__ C, long long sC,
    int K, int N, float alpha,
    const float* __restrict__ b1, const float* __restrict__ b2, long long sb)
{
    extern __shared__ float sm[];
    float* AsBase = sm;
    float* BsBase = sm + NSTG * STG_F;
    float* bias   = sm + 2 * NSTG * STG_F;
    const uint32_t smb = smem_u32(sm);

    const int tid  = threadIdx.x;
    const int wid  = tid >> 5, lane = tid & 31;
    const int wm   = wid >> 2, wn = wid & 3;
    const int g    = lane >> 2, tg = lane & 3;

    A += (size_t)blockIdx.z * sA;
    B += (size_t)blockIdx.z * sB;
    C += (size_t)blockIdx.z * sC;
    const int bm = blockIdx.y * 128;
    const int bn = blockIdx.x * 128;

    if (tid < 128) {
        float v = 0.f;
        if (b1) v += b1[blockIdx.z * sb + bn + tid];
        if (b2) v += b2[blockIdx.z * sb + bn + tid];
        bias[tid] = v;
    }

    const int lr = tid >> 3;
    const int c4 = tid & 7;
    const float* Ag0 = A + (size_t)bm * K + c4 * 4;
    const float* Bg0 = B + (size_t)bn * K + c4 * 4;

#define LOADCH(ch, st) do {                                                  \
        const uint32_t abase = smb + (uint32_t)(st) * (STG_F * 4);           \
        const uint32_t bbase = smb + (uint32_t)(NSTG + (st)) * (STG_F * 4);  \
        const float* Ac = Ag0 + (ch) * 32;                                   \
        const float* Bc = Bg0 + (ch) * 32;                                   \
        _Pragma("unroll")                                                    \
        for (int i = 0; i < 4; i++) {                                        \
            const int row = lr + 32 * i;                                     \
            const uint32_t off = (uint32_t)(row * GP + c4 * 4) * 4;          \
            cp16(abase + off, Ac + (size_t)row * K);                         \
            cp16(bbase + off, Bc + (size_t)row * K);                         \
        } } while (0)

    float acc[4][4][4];
#pragma unroll
    for (int mt = 0; mt < 4; mt++)
#pragma unroll
        for (int nt = 0; nt < 4; nt++)
#pragma unroll
            for (int e = 0; e < 4; e++) acc[mt][nt][e] = 0.f;

    const int nch = K >> 5;
    LOADCH(0, 0); CP_COMMIT();
    LOADCH(1, 1); CP_COMMIT();

    for (int i = 0; i < nch; i++) {
        const int s = i % 3;
        if (i + 2 < nch) CP_WAIT1(); else CP_WAIT0();
        __syncthreads();
        if (i + 2 < nch) { LOADCH(i + 2, (i + 2) % 3); CP_COMMIT(); }

        const float* As = AsBase + s * STG_F;
        const float* Bs = BsBase + s * STG_F;
        const uint32_t* Asu = (const uint32_t*)As;
        const uint32_t* Bsu = (const uint32_t*)Bs;
#pragma unroll
        for (int ks = 0; ks < 4; ks++) {
            uint32_t af[4][4], bf[4][2];
#pragma unroll
            for (int mt = 0; mt < 4; mt++) {
                const int r = (wm * 64 + mt * 16 + g) * GP + ks * 8 + tg;
                if (CVTA) {
                    af[mt][0] = f2tf(As[r]);
                    af[mt][1] = f2tf(As[r + 8 * GP]);
                    af[mt][2] = f2tf(As[r + 4]);
                    af[mt][3] = f2tf(As[r + 8 * GP + 4]);
                } else {
                    af[mt][0] = Asu[r];
                    af[mt][1] = Asu[r + 8 * GP];
                    af[mt][2] = Asu[r + 4];
                    af[mt][3] = Asu[r + 8 * GP + 4];
                }
            }
#pragma unroll
            for (int nt = 0; nt < 4; nt++) {
                const int r = (wn * 32 + nt * 8 + g) * GP + ks * 8 + tg;
                if (CVTB) {
                    bf[nt][0] = f2tf(Bs[r]);
                    bf[nt][1] = f2tf(Bs[r + 4]);
                } else {
                    bf[nt][0] = Bsu[r];
                    bf[nt][1] = Bsu[r + 4];
                }
            }
#pragma unroll
            for (int mt = 0; mt < 4; mt++)
#pragma unroll
                for (int nt = 0; nt < 4; nt++)
                    mma8(acc[mt][nt], af[mt], bf[nt]);
        }
    }
    __syncthreads();

#pragma unroll
    for (int mt = 0; mt < 4; mt++) {
        const int r0 = bm + wm * 64 + mt * 16 + g;
#pragma unroll
        for (int nt = 0; nt < 4; nt++) {
            const int cl = wn * 32 + nt * 8 + 2 * tg;
            const int c0 = bn + cl;
            float2 o0, o1;
            o0.x = acc[mt][nt][0] * alpha + bias[cl];
            o0.y = acc[mt][nt][1] * alpha + bias[cl + 1];
            o1.x = acc[mt][nt][2] * alpha + bias[cl];
            o1.y = acc[mt][nt][3] * alpha + bias[cl + 1];
            if (ROUNDC) {
                o0.x = roundtf(o0.x); o0.y = roundtf(o0.y);
                o1.x = roundtf(o1.x); o1.y = roundtf(o1.y);
            }
            *(float2*)(C + (size_t)r0 * N + c0)       = o0;
            *(float2*)(C + (size_t)(r0 + 8) * N + c0) = o1;
        }
    }
#undef LOADCH
}

// =============================================================================
// LSTM recurrence: 64 CTAs x 512 threads.
//  - Whh K 0..95 in registers (f32x2 pairs), K 96..127 in smem [j4][g] u64x2
//  - activations distributed across all 512 threads (warp-uniform by gate type)
//  - fast inf-safe tanh via __expf
// =============================================================================
#define LSTM_SMEM ((128 + 512) * 4 + 8 * 512 * 16)   // 68096 B

__device__ __forceinline__ void fma2(unsigned long long& d,
                                     unsigned long long a,
                                     unsigned long long b)
{
    asm("fma.rn.f32x2 %0, %1, %2, %0;" : "+l"(d) : "l"(a), "l"(b));
}
__device__ __forceinline__ float sum2(unsigned long long a)
{
    return __uint_as_float((unsigned)a) + __uint_as_float((unsigned)(a >> 32));
}
__device__ __forceinline__ float ftanh(float x)
{
    float ax = fabsf(x);
    float e = __expf(2.f * ax);          // inf for large ax -> t == 1
    float t = 1.f - 2.f / (e + 1.f);
    return copysignf(t, x);
}

__global__ __launch_bounds__(512) void lstm_kernel(
    const float* __restrict__ xg_all,
    const float* __restrict__ Whh_fw,
    const float* __restrict__ Whh_bw,
    float* __restrict__ Hout)
{
    extern __shared__ float sm[];
    float* h_sh = sm;                                  // 128
    float* gate = sm + 128;                            // 512 (activated)
    ulonglong2* w_shq = (ulonglong2*)(sm + 640);       // [j4][g]: 8*512

    const int dir = blockIdx.x >> 5;
    const int b   = blockIdx.x & 31;
    const int g   = threadIdx.x;
    const float* Whh = dir ? Whh_bw : Whh_fw;

    // register half: K 0..95 (48 f32x2 pairs)
    unsigned long long w2[48];
    {
        const unsigned long long* wr =
            (const unsigned long long*)(Whh + (size_t)g * HH);
#pragma unroll
        for (int i = 0; i < 48; i++) w2[i] = wr[i];
    }
    // smem half: K 96..127 as ulonglong2 [j4][g] (conflict-free LDS.128)
    {
        const ulonglong2* wsrc =
            (const ulonglong2*)(Whh + (size_t)g * HH + 96);
#pragma unroll
        for (int j4 = 0; j4 < 8; j4++) w_shq[j4 * 512 + g] = wsrc[j4];
    }
    if (g < HH) h_sh[g] = 0.f;
    float c = 0.f;
    __syncthreads();

    const float* xg = xg_all + ((size_t)dir * BB + b) * SS * (4 * HH);
    float xg_cur = __ldcs(xg + (size_t)(dir ? SS - 1 : 0) * 512 + g);

    const int gtype = g >> 7;                 // 0:i 1:f 2:g 3:o (warp-uniform)

    for (int t = 0; t < SS; t++) {
        const int s = dir ? (SS - 1 - t) : t;
        float acc = xg_cur;
        if (t + 1 < SS) {
            const int sn = dir ? (SS - 2 - t) : (t + 1);
            xg_cur = __ldcs(xg + (size_t)sn * 512 + g);
        }

        unsigned long long a2a = 0ull, a2b = 0ull;
        const ulonglong2* hq = (const ulonglong2*)h_sh;    // 32 x (2 pairs)
#pragma unroll
        for (int i = 0; i < 24; i++) {                     // pairs 0..47 (regs)
            ulonglong2 hv = hq[i];
            fma2(a2a, w2[2 * i], hv.x);
            fma2(a2b, w2[2 * i + 1], hv.y);
        }
#pragma unroll
        for (int j4 = 0; j4 < 8; j4++) {                   // pairs 48..63 (smem)
            ulonglong2 wv = w_shq[j4 * 512 + g];
            ulonglong2 hv = hq[24 + j4];
            fma2(a2a, wv.x, hv.x);
            fma2(a2b, wv.y, hv.y);
        }
        acc += sum2(a2a) + sum2(a2b);

        // distributed activation (gate-type uniform per warp)
        gate[g] = (gtype == 2) ? ftanh(acc)
                               : 1.f / (1.f + __expf(-acc));
        __syncthreads();

        if (g < HH) {
            const float i_ = gate[g];
            const float f_ = gate[HH + g];
            const float g_ = gate[2 * HH + g];
            const float o_ = gate[3 * HH + g];
            c = f_ * c + i_ * g_;
            const float h = o_ * ftanh(c);
            h_sh[g] = h;
            Hout[((size_t)b * SS + s) * DD + dir * HH + g] = roundtf(h);
        }
        __syncthreads();
    }
}

// =============================================================================
// Row softmax; output tf32-rounded
// =============================================================================
__global__ __launch_bounds__(256) void softmax_rows(float* __restrict__ S)
{
    float* row = S + (size_t)blockIdx.x * SS;
    const int t = threadIdx.x;
    __shared__ float red[8];

    float v0 = row[t], v1 = row[t + 256], v2 = row[t + 512], v3 = row[t + 768];

    float m = fmaxf(fmaxf(v0, v1), fmaxf(v2, v3));
#pragma unroll
    for (int o = 16; o > 0; o >>= 1)
        m = fmaxf(m, __shfl_xor_sync(0xffffffffu, m, o));
    if ((t & 31) == 0) red[t >> 5] = m;
    __syncthreads();
    m = fmaxf(fmaxf(fmaxf(red[0], red[1]), fmaxf(red[2], red[3])),
              fmaxf(fmaxf(red[4], red[5]), fmaxf(red[6], red[7])));

    v0 = __expf(v0 - m); v1 = __expf(v1 - m);
    v2 = __expf(v2 - m); v3 = __expf(v3 - m);
    float s = (v0 + v1) + (v2 + v3);
#pragma unroll
    for (int o = 16; o > 0; o >>= 1)
        s += __shfl_xor_sync(0xffffffffu, s, o);
    __syncthreads();
    if ((t & 31) == 0) red[t >> 5] = s;
    __syncthreads();
    s = ((red[0] + red[1]) + (red[2] + red[3])) +
        ((red[4] + red[5]) + (red[6] + red[7]));
    const float inv = 1.f / s;

    row[t]       = roundtf(v0 * inv);
    row[t + 256] = roundtf(v1 * inv);
    row[t + 512] = roundtf(v2 * inv);
    row[t + 768] = roundtf(v3 * inv);
}

// =============================================================================
// launch
// =============================================================================
extern "C" void kernel_launch(void* const* d_in, const int* in_sizes, int n_in,
                              void* d_out, int out_size)
{
    const float* x     = (const float*)d_in[0];
    const float* fwWih = (const float*)d_in[1];
    const float* fwWhh = (const float*)d_in[2];
    const float* fwbih = (const float*)d_in[3];
    const float* fwbhh = (const float*)d_in[4];
    const float* bwWih = (const float*)d_in[5];
    const float* bwWhh = (const float*)d_in[6];
    const float* bwbih = (const float*)d_in[7];
    const float* bwbhh = (const float*)d_in[8];
    const float* Wq    = (const float*)d_in[9];
    const float* Wk    = (const float*)d_in[10];
    const float* Wv    = (const float*)d_in[11];
    float* out = (float*)d_out;

    float *xg, *h, *qk, *v, *sc, *wqk, *wih, *b1s, *b2s;
    cudaGetSymbolAddress((void**)&xg,  g_xg);
    cudaGetSymbolAddress((void**)&h,   g_h);
    cudaGetSymbolAddress((void**)&qk,  g_qk);
    cudaGetSymbolAddress((void**)&v,   g_v);
    cudaGetSymbolAddress((void**)&sc,  g_sc);
    cudaGetSymbolAddress((void**)&wqk, g_wqk);
    cudaGetSymbolAddress((void**)&wih, g_wih);
    cudaGetSymbolAddress((void**)&b1s, g_b1);
    cudaGetSymbolAddress((void**)&b2s, g_b2);

    cudaFuncSetAttribute(mma_gemm_nt<true, true, false>,
                         cudaFuncAttributeMaxDynamicSharedMemorySize, GEMM_SMEM);
    cudaFuncSetAttribute(mma_gemm_nt<false, true, true>,
                         cudaFuncAttributeMaxDynamicSharedMemorySize, GEMM_SMEM);
    cudaFuncSetAttribute(mma_gemm_nt<true, false, true>,
                         cudaFuncAttributeMaxDynamicSharedMemorySize, GEMM_SMEM);
    cudaFuncSetAttribute(mma_gemm_nt<false, false, false>,
                         cudaFuncAttributeMaxDynamicSharedMemorySize, GEMM_SMEM);
    cudaFuncSetAttribute(lstm_kernel,
                         cudaFuncAttributeMaxDynamicSharedMemorySize, LSTM_SMEM);

    const long long SD  = (long long)SS * DD;
    const long long SS2 = (long long)SS * SS;
    const long long BSD = (long long)BB * SS * DD;
    const long long WIH = (long long)4 * HH * II;

    // stage weight/bias pairs adjacently for z=2 merged launches (D2D async)
    cudaMemcpyAsync(wqk,           Wq,    sizeof(float) * DD * DD,
                    cudaMemcpyDeviceToDevice);
    cudaMemcpyAsync(wqk + DD * DD, Wk,    sizeof(float) * DD * DD,
                    cudaMemcpyDeviceToDevice);
    cudaMemcpyAsync(wih,           fwWih, sizeof(float) * WIH,
                    cudaMemcpyDeviceToDevice);
    cudaMemcpyAsync(wih + WIH,     bwWih, sizeof(float) * WIH,
                    cudaMemcpyDeviceToDevice);
    cudaMemcpyAsync(b1s,           fwbih, sizeof(float) * 4 * HH,
                    cudaMemcpyDeviceToDevice);
    cudaMemcpyAsync(b1s + 4 * HH,  bwbih, sizeof(float) * 4 * HH,
                    cudaMemcpyDeviceToDevice);
    cudaMemcpyAsync(b2s,           fwbhh, sizeof(float) * 4 * HH,
                    cudaMemcpyDeviceToDevice);
    cudaMemcpyAsync(b2s + 4 * HH,  bwbhh, sizeof(float) * 4 * HH,
                    cudaMemcpyDeviceToDevice);

    // 1) xg[dir] = x @ Wih[dir]^T + biases   (merged fw/bw, z=2)
    mma_gemm_nt<true, true, false><<<dim3(4, 256, 2), 256, GEMM_SMEM>>>(
        x, 0, wih, WIH, xg, (long long)BB * SS * 4 * HH,
        II, 4 * HH, 1.f, b1s, b2s, 4 * HH);

    // 2) bidirectional LSTM recurrence -> h [B,S,2H] (rounded)
    lstm_kernel<<<64, 512, LSTM_SMEM>>>(xg, fwWhh, bwWhh, h);

    // 3) q,k projections merged (z=2): A=h pre-rounded, B=wqk raw; round C
    mma_gemm_nt<false, true, true><<<dim3(2, 256, 2), 256, GEMM_SMEM>>>(
        h, 0, wqk, (long long)DD * DD, qk, BSD, DD, DD, 1.f,
        nullptr, nullptr, 0);

    // 3b) vT[b][d][t] = Wv @ h[b]^T: cvtA for Wv, B=h pre-rounded; round C
    mma_gemm_nt<true, false, true><<<dim3(8, 2, 32), 256, GEMM_SMEM>>>(
        Wv, 0, h, SD, v, SD, DD, SS, 1.f, nullptr, nullptr, 0);

    // 4) scores = q @ k^T / 16: both pre-rounded, no cvt
    mma_gemm_nt<false, false, false><<<dim3(8, 8, 32), 256, GEMM_SMEM>>>(
        qk, SD, qk + BSD, SD, sc, SS2, DD, SS, 0.0625f, nullptr, nullptr, 0);

    // 5) softmax (rounds output)
    softmax_rows<<<BB * SS, 256>>>(sc);

    // 6) out = att @ vT^T: both pre-rounded, no cvt
    mma_gemm_nt<false, false, false><<<dim3(2, 8, 32), 256, GEMM_SMEM>>>(
        sc, SS2, v, SD, out, SD, SS, DD, 1.f, nullptr, nullptr, 0);
}